// round 10
// baseline (speedup 1.0000x reference)
#include <cuda_runtime.h>
#include <stdint.h>
#include <math.h>

// Problem constants
#define BATCH 2
#define TSEQ  1024
#define HDIM  1024
#define NTOK  (BATCH*TSEQ)     // 2048
#define NHEAD 16
#define NKVH  4
#define HEADD 64
#define NEXP  64
#define TOPK  8
#define IDIM  512

// ---------------- scratch (device globals; no allocations allowed) ----------
__device__ __align__(256) float g_h[NTOK*HDIM];
__device__ __align__(256) float g_q[NTOK*NHEAD*HEADD];
__device__ __align__(256) float g_k[NTOK*NKVH*HEADD];
__device__ __align__(256) float g_v[NTOK*NKVH*HEADD];
__device__ __align__(256) float g_ao[NTOK*HDIM];
__device__ __align__(256) float g_f[NTOK*HDIM];
__device__ int   g_cnt[NEXP];
__device__ int   g_elist[NEXP*NTOK];
__device__ float g_escore[NEXP*NTOK];
__device__ __align__(256) float g_gbuf[(size_t)NEXP*NTOK*IDIM];
// transposed, tf32-rounded, k-permuted weights
__device__ __align__(256) float g_wqkvT[1536*1024];            // rows: q 0-1023, k 1024-1279, v 1280-1535
__device__ __align__(256) float g_woT[1024*1024];
__device__ __align__(256) float g_wrT[64*1024];
__device__ __align__(256) float g_wgT[(size_t)NEXP*IDIM*HDIM]; // [e][n=I][k=H]
__device__ __align__(256) float g_wuT[(size_t)NEXP*IDIM*HDIM];
__device__ __align__(256) float g_wdT[(size_t)NEXP*HDIM*IDIM]; // [e][n=H][k=I]

// ---------------- helpers ----------------------------------------------------
__device__ __forceinline__ float tf32r(float x) {
    uint32_t u;
    asm("cvt.rna.tf32.f32 %0, %1;" : "=r"(u) : "f"(x));
    return __uint_as_float(u);
}
// k-permutation within each 16-element group: pos 4a+b -> 4b+a (self-inverse)
__device__ __forceinline__ int permc(int i) {
    return (i & ~15) | (((i & 3) << 2) | ((i >> 2) & 3));
}
__device__ __forceinline__ void mma8(float* c, const uint32_t* a, const uint32_t* b) {
    asm volatile(
        "mma.sync.aligned.m16n8k8.row.col.f32.tf32.tf32.f32 "
        "{%0,%1,%2,%3}, {%4,%5,%6,%7}, {%8,%9}, {%0,%1,%2,%3};"
        : "+f"(c[0]), "+f"(c[1]), "+f"(c[2]), "+f"(c[3])
        : "r"(a[0]), "r"(a[1]), "r"(a[2]), "r"(a[3]), "r"(b[0]), "r"(b[1]));
}
__device__ __forceinline__ void cp16(uint32_t dst, const void* src, int sz) {
    asm volatile("cp.async.cg.shared.global [%0], [%1], 16, %2;"
                 :: "r"(dst), "l"(src), "r"(sz));
}

// ---------------- weight conversion: W[K][N] -> WT[n][K] tf32 + k-permuted ---
__global__ void wconv_kernel(const float* __restrict__ W, float* __restrict__ WT,
                             int K, int N, size_t wz, size_t tz) {
    W  += (size_t)blockIdx.z * wz;
    WT += (size_t)blockIdx.z * tz;
    __shared__ float tile[32][33];
    int k0 = blockIdx.y * 32, n0 = blockIdx.x * 32;
    int tx = threadIdx.x & 31, ty = threadIdx.x >> 5;  // 32x8
    #pragma unroll
    for (int i = ty; i < 32; i += 8)
        tile[i][tx] = W[(size_t)(k0 + i) * N + n0 + tx];
    __syncthreads();
    #pragma unroll
    for (int i = ty; i < 32; i += 8)
        WT[(size_t)(n0 + i) * K + k0 + permc(tx)] = tf32r(tile[tx][i]);
}

// ---------------- rmsnorm (writes tf32-rounded, k-permuted) ------------------
__global__ void rmsnorm_kernel(const float* __restrict__ x,
                               const float* __restrict__ w,
                               float* __restrict__ o) {
    int row = blockIdx.x;
    const float* xr = x + (size_t)row * HDIM;
    __shared__ float red[256];
    float s = 0.f;
    for (int i = threadIdx.x; i < HDIM; i += 256) { float v = xr[i]; s += v * v; }
    red[threadIdx.x] = s;
    __syncthreads();
    for (int st = 128; st > 0; st >>= 1) {
        if (threadIdx.x < st) red[threadIdx.x] += red[threadIdx.x + st];
        __syncthreads();
    }
    float inv = rsqrtf(red[0] / (float)HDIM + 1e-6f);
    for (int i = threadIdx.x; i < HDIM; i += 256)
        o[(size_t)row * HDIM + permc(i)] = tf32r(xr[i] * inv * w[i]);
}

// ---------------- tf32 tensor-core GEMM v3 ----------------------------------
// 128x128x16 tile, 128 threads (4 warps 2x2, warp tile 64x64).
// A: pre-rounded/permuted rows [m][K]; B: transposed weights WT [n][K].
// Both smem tiles [row][16] plain (64B row stride = conflict-free float4 frags).
// MODE 0: C = A@B (+R), col guard N
// MODE 1: MoE gate: gathered A rows -> gbuf (plain)
// MODE 2: MoE up:   gathered A; epi (two-pass): gb = silu(gb)*acc*score,
//                   tf32+permuted (gbuf becomes A of down GEMM)
// MODE 3: MoE down: A = gbuf slice; epi: atomicAdd into out
// MODE 4: fused QKV (concatenated wqkvT); C routed among q/k/v
#define TB 128
#define TSZ (128*16)
#define STG 4
#define GEMM_SMEM ((STG*2*TSZ)*4 + TB*4)

template<int MODE>
__launch_bounds__(TB, 2)
__global__ void mma_gemm(const float* __restrict__ A, const float* __restrict__ BT,
                         const float* __restrict__ R, float* __restrict__ C,
                         int M, int N, int K,
                         const int* __restrict__ cnt, const int* __restrict__ elist,
                         const float* __restrict__ escore,
                         float* __restrict__ C2, float* __restrict__ C3) {
    extern __shared__ float sh[];
    float* As = sh;
    float* Bs = sh + STG * TSZ;
    int* rows = (int*)(sh + STG * 2 * TSZ);

    const int t = threadIdx.x;
    int e = 0, c = M;
    const int t0 = blockIdx.y * 128;
    const int by = t0;
    const int bx = blockIdx.x * 128;

    // output routing
    float* Cp = C; int cstr = N; int ccol = bx;
    if (MODE == 4) {
        if (bx < 1024)      { Cp = C;  cstr = 1024; ccol = bx; }
        else if (bx < 1280) { Cp = C2; cstr = 256;  ccol = bx - 1024; }
        else                { Cp = C3; cstr = 256;  ccol = bx - 1280; }
    }
    const float* Bp = BT;
    if (MODE >= 1 && MODE <= 3) {
        e = blockIdx.z;
        c = cnt[e];
        if (t0 >= c) return;
        Bp = BT + (size_t)e * N * K;
        if (MODE <= 2) {
            if (t < 128) {
                int tr = t0 + t;
                rows[t] = elist[e * NTOK + (tr < c ? tr : c - 1)];
            }
            __syncthreads();
        } else {
            A += (size_t)e * NTOK * K;
        }
    }

    const int lane = t & 31, warp = t >> 5;
    const int lr = lane >> 2, lq = lane & 3;
    const int m0w = (warp & 1) * 64, n0w = (warp >> 1) * 64;

    const uint32_t sAu = (uint32_t)__cvta_generic_to_shared(As);
    const uint32_t sBu = (uint32_t)__cvta_generic_to_shared(Bs);

    float acc[4][8][4] = {};
    const int KT = K / 16;

    auto issue = [&](int buf, int k0) {
        uint32_t dA = sAu + buf * TSZ * 4;
        uint32_t dB = sBu + buf * TSZ * 4;
        #pragma unroll
        for (int i = 0; i < 4; i++) {
            int f = i * TB + t;
            int r = f >> 2, seg = f & 3;
            int gr;
            if (MODE == 0 || MODE == 4) gr = by + r;
            else if (MODE == 3) gr = t0 + r;
            else gr = rows[r];
            cp16(dA + (r * 16 + seg * 4) * 4, A + (size_t)gr * K + k0 + seg * 4, 16);
            int n = bx + r;
            const float* srcB = Bp + (size_t)(n < N ? n : 0) * K + k0 + seg * 4;
            cp16(dB + (r * 16 + seg * 4) * 4, srcB, n < N ? 16 : 0);
        }
    };

    #pragma unroll
    for (int s = 0; s < STG - 1; s++) {
        issue(s, s * 16);
        asm volatile("cp.async.commit_group;");
    }
    for (int it = 0; it < KT; it++) {
        if (it + STG - 1 < KT) issue((it + STG - 1) % STG, (it + STG - 1) * 16);
        asm volatile("cp.async.commit_group;");
        asm volatile("cp.async.wait_group %0;" :: "n"(STG - 1));
        __syncthreads();
        const float* Ab = As + (it % STG) * TSZ;
        const float* Bb = Bs + (it % STG) * TSZ;

        uint32_t a0[4][4], a1[4][4];
        #pragma unroll
        for (int mt = 0; mt < 4; mt++) {
            int m = m0w + mt * 16 + lr;
            float4 va = *(const float4*)&Ab[m * 16 + 4 * lq];
            float4 vb = *(const float4*)&Ab[(m + 8) * 16 + 4 * lq];
            a0[mt][0] = __float_as_uint(va.x); a0[mt][1] = __float_as_uint(vb.x);
            a0[mt][2] = __float_as_uint(va.y); a0[mt][3] = __float_as_uint(vb.y);
            a1[mt][0] = __float_as_uint(va.z); a1[mt][1] = __float_as_uint(vb.z);
            a1[mt][2] = __float_as_uint(va.w); a1[mt][3] = __float_as_uint(vb.w);
        }
        uint32_t b0[8][2], b1[8][2];
        #pragma unroll
        for (int nt = 0; nt < 8; nt++) {
            int n = n0w + nt * 8 + lr;
            float4 vB = *(const float4*)&Bb[n * 16 + 4 * lq];
            b0[nt][0] = __float_as_uint(vB.x); b0[nt][1] = __float_as_uint(vB.y);
            b1[nt][0] = __float_as_uint(vB.z); b1[nt][1] = __float_as_uint(vB.w);
        }
        #pragma unroll
        for (int mt = 0; mt < 4; mt++)
            #pragma unroll
            for (int nt = 0; nt < 8; nt++) {
                mma8(acc[mt][nt], a0[mt], b0[nt]);
                mma8(acc[mt][nt], a1[mt], b1[nt]);
            }
        __syncthreads();
    }

    // ---------------- epilogue ----------------
    if (MODE == 2) {
        // pass 1: read gate (plain layout), combine into acc. No writes yet —
        // the permuted store moves data across columns other threads still read.
        #pragma unroll
        for (int mt = 0; mt < 4; mt++)
            #pragma unroll
            for (int i = 0; i < 2; i++) {
                int r = m0w + mt * 16 + lr + i * 8;
                int tr = t0 + r;
                if (tr >= c) continue;
                float sc = escore[e * NTOK + tr];
                #pragma unroll
                for (int nt = 0; nt < 8; nt++) {
                    int col = bx + n0w + nt * 8 + lq * 2;
                    size_t o = ((size_t)e * NTOK + tr) * N + col;
                    float g0 = C[o], g1 = C[o + 1];
                    acc[mt][nt][i * 2]     = tf32r(g0 / (1.f + expf(-g0)) * acc[mt][nt][i * 2]     * sc);
                    acc[mt][nt][i * 2 + 1] = tf32r(g1 / (1.f + expf(-g1)) * acc[mt][nt][i * 2 + 1] * sc);
                }
            }
        __syncthreads();   // all reads complete before any permuted write
        // pass 2: write permuted (gbuf becomes A of down GEMM)
        #pragma unroll
        for (int mt = 0; mt < 4; mt++)
            #pragma unroll
            for (int i = 0; i < 2; i++) {
                int r = m0w + mt * 16 + lr + i * 8;
                int tr = t0 + r;
                if (tr >= c) continue;
                #pragma unroll
                for (int nt = 0; nt < 8; nt++) {
                    int col = bx + n0w + nt * 8 + lq * 2;
                    size_t ob = ((size_t)e * NTOK + tr) * N;
                    int pc = permc(col);
                    C[ob + pc]     = acc[mt][nt][i * 2];
                    C[ob + pc + 4] = acc[mt][nt][i * 2 + 1];  // permc(col+1)=permc(col)+4 for even col
                }
            }
        return;
    }
    #pragma unroll
    for (int mt = 0; mt < 4; mt++)
        #pragma unroll
        for (int i = 0; i < 2; i++) {
            int r = m0w + mt * 16 + lr + i * 8;
            #pragma unroll
            for (int nt = 0; nt < 8; nt++) {
                int col = ccol + n0w + nt * 8 + lq * 2;
                float v0 = acc[mt][nt][i * 2 + 0];
                float v1 = acc[mt][nt][i * 2 + 1];
                if (MODE == 0 || MODE == 4) {
                    if (col < cstr && (MODE == 4 || col < N)) {
                        int gr = by + r;
                        size_t o = (size_t)gr * cstr + col;
                        if (MODE == 0 && R) { v0 += R[o]; v1 += R[o + 1]; }
                        Cp[o] = v0; Cp[o + 1] = v1;
                    }
                } else {
                    int tr = t0 + r;
                    if (tr < c) {
                        int cc = bx + n0w + nt * 8 + lq * 2;
                        if (MODE == 1) {
                            size_t o = ((size_t)e * NTOK + tr) * N + cc;
                            C[o] = v0; C[o + 1] = v1;
                        } else {  // MODE 3
                            int n = elist[e * NTOK + tr];
                            atomicAdd(&C[(size_t)n * N + cc], v0);
                            atomicAdd(&C[(size_t)n * N + cc + 1], v1);
                        }
                    }
                }
            }
        }
}

// ---------------- RoPE (in place) -------------------------------------------
__global__ void rope_kernel(float* __restrict__ q, const float* __restrict__ cs,
                            const float* __restrict__ sn, int nheads) {
    int idx = blockIdx.x * blockDim.x + threadIdx.x;
    int total = NTOK * nheads * 32;
    if (idx >= total) return;
    int d  = idx & 31;
    int hh = (idx >> 5) % nheads;
    int n  = idx / (32 * nheads);
    int tp = n % TSEQ;
    float c0 = cs[tp * HEADD + d],      s0 = sn[tp * HEADD + d];
    float c1 = cs[tp * HEADD + d + 32], s1 = sn[tp * HEADD + d + 32];
    float* base = q + ((size_t)n * nheads + hh) * HEADD;
    float v0 = base[d], v1 = base[d + 32];
    base[d]      = v0 * c0 - v1 * s0;
    base[d + 32] = v1 * c1 + v0 * s1;
}

// ---------------- tiled causal flash attention ------------------------------
// Output written tf32-rounded + k-permuted (feeds Wo GEMM as A).
__global__ void attn_kernel(const float* __restrict__ Q, const float* __restrict__ Kg,
                            const float* __restrict__ Vg, float* __restrict__ O) {
    extern __shared__ float sm[];
    float* Qs = sm;                       // [64][65]
    float* Ks = sm + 64 * 65;             // [64][65]
    float* Vs = sm + 2 * 64 * 65;         // [64][68]
    float* Ss = sm + 2 * 64 * 65 + 64 * 68; // [64][65]
    __shared__ float m_s[64], l_s[64], corr_s[64];

    int qt = (int)gridDim.x - 1 - (int)blockIdx.x;
    int h = blockIdx.y, b = blockIdx.z;
    int kvh = h >> 2;
    int t = threadIdx.x, ty = t >> 4, tx = t & 15;
    int q0 = ty * 4, d0c = tx * 4;

    {
        int r = t >> 2, d0 = (t & 3) * 16;
        int n = b * TSEQ + qt * 64 + r;
        const float* src = Q + ((size_t)n * NHEAD + h) * 64 + d0;
        #pragma unroll
        for (int j = 0; j < 16; j += 4) {
            float4 v = *(const float4*)(src + j);
            Qs[r * 65 + d0 + j]     = v.x;
            Qs[r * 65 + d0 + j + 1] = v.y;
            Qs[r * 65 + d0 + j + 2] = v.z;
            Qs[r * 65 + d0 + j + 3] = v.w;
        }
    }
    if (t < 64) { m_s[t] = -1e30f; l_s[t] = 0.f; }

    float o[4][4];
    #pragma unroll
    for (int i = 0; i < 4; i++)
        #pragma unroll
        for (int j = 0; j < 4; j++) o[i][j] = 0.f;

    for (int kt = 0; kt <= qt; kt++) {
        __syncthreads();
        {
            int r = t >> 2, dd0 = (t & 3) * 16;
            int kn = b * TSEQ + kt * 64 + r;
            const float* ks = Kg + ((size_t)kn * NKVH + kvh) * 64 + dd0;
            const float* vs = Vg + ((size_t)kn * NKVH + kvh) * 64 + dd0;
            #pragma unroll
            for (int j = 0; j < 16; j += 4) {
                float4 kv = *(const float4*)(ks + j);
                Ks[r * 65 + dd0 + j]     = kv.x;
                Ks[r * 65 + dd0 + j + 1] = kv.y;
                Ks[r * 65 + dd0 + j + 2] = kv.z;
                Ks[r * 65 + dd0 + j + 3] = kv.w;
                float4 vv = *(const float4*)(vs + j);
                *(float4*)&Vs[r * 68 + dd0 + j] = vv;
            }
        }
        __syncthreads();
        float s4[4][4];
        #pragma unroll
        for (int i = 0; i < 4; i++)
            #pragma unroll
            for (int j = 0; j < 4; j++) s4[i][j] = 0.f;
        for (int d = 0; d < 64; d++) {
            float a[4], bb[4];
            #pragma unroll
            for (int i = 0; i < 4; i++) a[i] = Qs[(q0 + i) * 65 + d];
            #pragma unroll
            for (int j = 0; j < 4; j++) bb[j] = Ks[(d0c + j) * 65 + d];
            #pragma unroll
            for (int i = 0; i < 4; i++)
                #pragma unroll
                for (int j = 0; j < 4; j++) s4[i][j] += a[i] * bb[j];
        }
        #pragma unroll
        for (int i = 0; i < 4; i++)
            #pragma unroll
            for (int j = 0; j < 4; j++) {
                int kglob = kt * 64 + d0c + j, qglob = qt * 64 + q0 + i;
                Ss[(q0 + i) * 65 + d0c + j] =
                    (kglob <= qglob) ? s4[i][j] * 0.125f : -1e30f;
            }
        __syncthreads();
        if (t < 64) {
            float mx = -1e30f;
            for (int k = 0; k < 64; k++) mx = fmaxf(mx, Ss[t * 65 + k]);
            float newm = fmaxf(m_s[t], mx);
            float corr = expf(m_s[t] - newm);
            float sum = 0.f;
            for (int k = 0; k < 64; k++) sum += expf(Ss[t * 65 + k] - newm);
            l_s[t] = l_s[t] * corr + sum;
            m_s[t] = newm;
            corr_s[t] = corr;
        }
        __syncthreads();
        #pragma unroll
        for (int i = 0; i < 4; i++) {
            float nm = m_s[q0 + i];
            float cr = corr_s[q0 + i];
            #pragma unroll
            for (int j = 0; j < 4; j++) {
                float p = expf(Ss[(q0 + i) * 65 + d0c + j] - nm);
                Ss[(q0 + i) * 65 + d0c + j] = p;
                o[i][j] *= cr;
            }
        }
        __syncthreads();
        for (int k = 0; k < 64; k++) {
            float a[4];
            #pragma unroll
            for (int i = 0; i < 4; i++) a[i] = Ss[(q0 + i) * 65 + k];
            float4 bv = *(const float4*)&Vs[k * 68 + d0c];
            #pragma unroll
            for (int i = 0; i < 4; i++) {
                o[i][0] += a[i] * bv.x;
                o[i][1] += a[i] * bv.y;
                o[i][2] += a[i] * bv.z;
                o[i][3] += a[i] * bv.w;
            }
        }
    }
    #pragma unroll
    for (int i = 0; i < 4; i++) {
        float inv = 1.f / l_s[q0 + i];
        int n = b * TSEQ + qt * 64 + q0 + i;
        #pragma unroll
        for (int j = 0; j < 4; j++)
            O[(size_t)n * HDIM + permc(h * 64 + d0c + j)] = tf32r(o[i][j] * inv);
    }
}

// ---------------- router ----------------------------------------------------
__global__ void zero_cnt_kernel(int* __restrict__ cnt) {
    if (threadIdx.x < NEXP) cnt[threadIdx.x] = 0;
}

__global__ void router_topk_kernel(const float* __restrict__ logits,
                                   int* __restrict__ cnt, int* __restrict__ elist,
                                   float* __restrict__ escore) {
    int n = blockIdx.x * blockDim.x + threadIdx.x;
    if (n >= NTOK) return;
    float lg[NEXP];
    for (int e = 0; e < NEXP; e++) lg[e] = logits[(size_t)n * NEXP + e];
    int sel[TOPK]; float sv[TOPK];
    for (int k = 0; k < TOPK; k++) {
        float best = -1e30f; int bi = 0;
        for (int e = 0; e < NEXP; e++)
            if (lg[e] > best) { best = lg[e]; bi = e; }
        sel[k] = bi; sv[k] = best; lg[bi] = -1e30f;
    }
    float mx = sv[0];
    float ssum = 0.f;
    for (int k = 0; k < TOPK; k++) { sv[k] = expf(sv[k] - mx); ssum += sv[k]; }
    for (int k = 0; k < TOPK; k++) {
        int e = sel[k];
        int pos = atomicAdd(&cnt[e], 1);
        elist[e * NTOK + pos]  = n;
        escore[e * NTOK + pos] = sv[k] / ssum;
    }
}

// ---------------- launch ----------------------------------------------------
extern "C" void kernel_launch(void* const* d_in, const int* in_sizes, int n_in,
                              void* d_out, int out_size) {
    const float* x    = (const float*)d_in[0];
    const float* cosb = (const float*)d_in[1];
    const float* sinb = (const float*)d_in[2];
    const float* ln1  = (const float*)d_in[3];
    const float* ln2  = (const float*)d_in[4];
    const float* Wq   = (const float*)d_in[5];
    const float* Wk   = (const float*)d_in[6];
    const float* Wv   = (const float*)d_in[7];
    const float* Wo   = (const float*)d_in[8];
    const float* Wr   = (const float*)d_in[9];
    const float* Wg   = (const float*)d_in[10];
    const float* Wu   = (const float*)d_in[11];
    const float* Wd   = (const float*)d_in[12];
    float* out = (float*)d_out;
    float* rl  = out + (size_t)NTOK * HDIM;

    float *h, *q, *k, *v, *ao, *f, *gb, *es;
    float *wqkvT, *woT, *wrT, *wgT, *wuT, *wdT;
    int *cnt, *el;
    cudaGetSymbolAddress((void**)&h,   g_h);
    cudaGetSymbolAddress((void**)&q,   g_q);
    cudaGetSymbolAddress((void**)&k,   g_k);
    cudaGetSymbolAddress((void**)&v,   g_v);
    cudaGetSymbolAddress((void**)&ao,  g_ao);
    cudaGetSymbolAddress((void**)&f,   g_f);
    cudaGetSymbolAddress((void**)&gb,  g_gbuf);
    cudaGetSymbolAddress((void**)&es,  g_escore);
    cudaGetSymbolAddress((void**)&cnt, g_cnt);
    cudaGetSymbolAddress((void**)&el,  g_elist);
    cudaGetSymbolAddress((void**)&wqkvT, g_wqkvT);
    cudaGetSymbolAddress((void**)&woT, g_woT);
    cudaGetSymbolAddress((void**)&wrT, g_wrT);
    cudaGetSymbolAddress((void**)&wgT, g_wgT);
    cudaGetSymbolAddress((void**)&wuT, g_wuT);
    cudaGetSymbolAddress((void**)&wdT, g_wdT);

    const int ATTN_SMEM = (2 * 64 * 65 + 64 * 68 + 64 * 65) * 4;
    cudaFuncSetAttribute(attn_kernel, cudaFuncAttributeMaxDynamicSharedMemorySize,
                         ATTN_SMEM);
    cudaFuncSetAttribute(mma_gemm<0>, cudaFuncAttributeMaxDynamicSharedMemorySize, GEMM_SMEM);
    cudaFuncSetAttribute(mma_gemm<1>, cudaFuncAttributeMaxDynamicSharedMemorySize, GEMM_SMEM);
    cudaFuncSetAttribute(mma_gemm<2>, cudaFuncAttributeMaxDynamicSharedMemorySize, GEMM_SMEM);
    cudaFuncSetAttribute(mma_gemm<3>, cudaFuncAttributeMaxDynamicSharedMemorySize, GEMM_SMEM);
    cudaFuncSetAttribute(mma_gemm<4>, cudaFuncAttributeMaxDynamicSharedMemorySize, GEMM_SMEM);

    // 0. weight conversion (transpose + tf32 + k-permute)
    wconv_kernel<<<dim3(32, 32, 1),  256>>>(Wq, wqkvT,                    1024, 1024, 0, 0);
    wconv_kernel<<<dim3(8,  32, 1),  256>>>(Wk, wqkvT + 1024 * 1024,      1024, 256,  0, 0);
    wconv_kernel<<<dim3(8,  32, 1),  256>>>(Wv, wqkvT + 1280 * 1024,      1024, 256,  0, 0);
    wconv_kernel<<<dim3(32, 32, 1),  256>>>(Wo, woT,                      1024, 1024, 0, 0);
    wconv_kernel<<<dim3(2,  32, 1),  256>>>(Wr, wrT,                      1024, 64,   0, 0);
    wconv_kernel<<<dim3(16, 32, NEXP), 256>>>(Wg, wgT, 1024, 512, (size_t)1024 * 512, (size_t)1024 * 512);
    wconv_kernel<<<dim3(16, 32, NEXP), 256>>>(Wu, wuT, 1024, 512, (size_t)1024 * 512, (size_t)1024 * 512);
    wconv_kernel<<<dim3(32, 16, NEXP), 256>>>(Wd, wdT, 512, 1024, (size_t)512 * 1024, (size_t)512 * 1024);

    // 1. h = rmsnorm(x, ln1_w)  [tf32 + permuted]
    rmsnorm_kernel<<<NTOK, 256>>>(x, ln1, h);
    // 2. fused QKV projection
    mma_gemm<4><<<dim3(12, 16), TB, GEMM_SMEM>>>(h, wqkvT, nullptr, q, NTOK, 1536, 1024,
                                                 nullptr, nullptr, nullptr, k, v);
    // 3. RoPE
    rope_kernel<<<(NTOK * NHEAD * 32 + 255) / 256, 256>>>(q, cosb, sinb, NHEAD);
    rope_kernel<<<(NTOK * NKVH  * 32 + 255) / 256, 256>>>(k, cosb, sinb, NKVH);
    // 4. attention (output tf32 + permuted)
    attn_kernel<<<dim3(TSEQ / 64, NHEAD, BATCH), 256, ATTN_SMEM>>>(q, k, v, ao);
    // 5. x1 = x + ao@Wo
    mma_gemm<0><<<dim3(8, 16), TB, GEMM_SMEM>>>(ao, woT, x, out, NTOK, 1024, 1024,
                                                nullptr, nullptr, nullptr, nullptr, nullptr);
    // 6. f = rmsnorm(x1, ln2_w)  [tf32 + permuted]
    rmsnorm_kernel<<<NTOK, 256>>>(out, ln2, f);
    // 7. router logits
    mma_gemm<0><<<dim3(1, 16), TB, GEMM_SMEM>>>(f, wrT, nullptr, rl, NTOK, NEXP, 1024,
                                                nullptr, nullptr, nullptr, nullptr, nullptr);
    // 8-9. top-k + expert lists
    zero_cnt_kernel<<<1, 64>>>(cnt);
    router_topk_kernel<<<NTOK / 256, 256>>>(rl, cnt, el, es);
    // 10a. gate GEMM -> gbuf (plain)
    mma_gemm<1><<<dim3(IDIM / 128, NTOK / 128, NEXP), TB, GEMM_SMEM>>>(f, wgT, nullptr, gb, NTOK, IDIM, 1024,
                                                cnt, el, es, nullptr, nullptr);
    // 10b. up GEMM, fused silu(gate)*up*score -> gbuf (tf32 + permuted, two-pass)
    mma_gemm<2><<<dim3(IDIM / 128, NTOK / 128, NEXP), TB, GEMM_SMEM>>>(f, wuT, nullptr, gb, NTOK, IDIM, 1024,
                                                cnt, el, es, nullptr, nullptr);
    // 11. down GEMM + scatter-add onto residual in d_out
    mma_gemm<3><<<dim3(HDIM / 128, NTOK / 128, NEXP), TB, GEMM_SMEM>>>(gb, wdT, nullptr, out, NTOK, HDIM, IDIM,
                                                cnt, el, es, nullptr, nullptr);
}

// round 12
// speedup vs baseline: 1.2418x; 1.2418x over previous
#include <cuda_runtime.h>
#include <stdint.h>
#include <math.h>

// Problem constants
#define BATCH 2
#define TSEQ  1024
#define HDIM  1024
#define NTOK  (BATCH*TSEQ)     // 2048
#define NHEAD 16
#define NKVH  4
#define HEADD 64
#define NEXP  64
#define TOPK  8
#define IDIM  512

// ---------------- scratch (device globals; no allocations allowed) ----------
__device__ __align__(256) float g_h[NTOK*HDIM];
__device__ __align__(256) float g_q[NTOK*NHEAD*HEADD];
__device__ __align__(256) float g_k[NTOK*NKVH*HEADD];
__device__ __align__(256) float g_v[NTOK*NKVH*HEADD];
__device__ __align__(256) float g_ao[NTOK*HDIM];
__device__ __align__(256) float g_f[NTOK*HDIM];
__device__ int   g_cnt[NEXP];
__device__ int   g_elist[NEXP*NTOK];
__device__ float g_escore[NEXP*NTOK];
__device__ __align__(256) float g_gbuf[(size_t)NEXP*NTOK*IDIM];
// transposed, tf32-rounded, k-permuted weights (small dense ones only)
__device__ __align__(256) float g_wqkvT[1536*1024];   // rows: q 0-1023, k 1024-1279, v 1280-1535
__device__ __align__(256) float g_woT[1024*1024];
__device__ __align__(256) float g_wrT[64*1024];

// ---------------- helpers ----------------------------------------------------
__device__ __forceinline__ float tf32r(float x) {
    uint32_t u;
    asm("cvt.rna.tf32.f32 %0, %1;" : "=r"(u) : "f"(x));
    return __uint_as_float(u);
}
__device__ __forceinline__ uint32_t ldcvt(const float* p) {
    uint32_t u;
    asm("cvt.rna.tf32.f32 %0, %1;" : "=r"(u) : "f"(*p));
    return u;
}
// k-permutation within each 16-element group: pos 4a+b -> 4b+a (self-inverse)
__device__ __forceinline__ int permc(int i) {
    return (i & ~15) | (((i & 3) << 2) | ((i >> 2) & 3));
}
__device__ __forceinline__ void mma8(float* c, const uint32_t* a, const uint32_t* b) {
    asm volatile(
        "mma.sync.aligned.m16n8k8.row.col.f32.tf32.tf32.f32 "
        "{%0,%1,%2,%3}, {%4,%5,%6,%7}, {%8,%9}, {%0,%1,%2,%3};"
        : "+f"(c[0]), "+f"(c[1]), "+f"(c[2]), "+f"(c[3])
        : "r"(a[0]), "r"(a[1]), "r"(a[2]), "r"(a[3]), "r"(b[0]), "r"(b[1]));
}
__device__ __forceinline__ void cp16(uint32_t dst, const void* src, int sz) {
    asm volatile("cp.async.cg.shared.global [%0], [%1], 16, %2;"
                 :: "r"(dst), "l"(src), "r"(sz));
}

// ---------------- weight conversion: W[K][N] -> WT[n][K] tf32 + k-permuted ---
__global__ void wconv_kernel(const float* __restrict__ W, float* __restrict__ WT,
                             int K, int N) {
    __shared__ float tile[32][33];
    int k0 = blockIdx.y * 32, n0 = blockIdx.x * 32;
    int tx = threadIdx.x & 31, ty = threadIdx.x >> 5;  // 32x8
    #pragma unroll
    for (int i = ty; i < 32; i += 8)
        tile[i][tx] = W[(size_t)(k0 + i) * N + n0 + tx];
    __syncthreads();
    #pragma unroll
    for (int i = ty; i < 32; i += 8)
        WT[(size_t)(n0 + i) * K + k0 + permc(tx)] = tf32r(tile[tx][i]);
}

// ---------------- rmsnorm (writes tf32-rounded, k-permuted) ------------------
__global__ void rmsnorm_kernel(const float* __restrict__ x,
                               const float* __restrict__ w,
                               float* __restrict__ o) {
    int row = blockIdx.x;
    const float* xr = x + (size_t)row * HDIM;
    __shared__ float red[256];
    float s = 0.f;
    for (int i = threadIdx.x; i < HDIM; i += 256) { float v = xr[i]; s += v * v; }
    red[threadIdx.x] = s;
    __syncthreads();
    for (int st = 128; st > 0; st >>= 1) {
        if (threadIdx.x < st) red[threadIdx.x] += red[threadIdx.x + st];
        __syncthreads();
    }
    float inv = rsqrtf(red[0] / (float)HDIM + 1e-6f);
    for (int i = threadIdx.x; i < HDIM; i += 256)
        o[(size_t)row * HDIM + permc(i)] = tf32r(xr[i] * inv * w[i]);
}

// ---------------- tf32 tensor-core GEMM v3 ----------------------------------
// 128x128x16 tile, 128 threads (4 warps 2x2, warp tile 64x64).
// A: pre-rounded/permuted rows [m][K] (all producers are mine).
// B: MODE 0/4 -> converted WT [n][K], float4 frags, no cvt.
//    MODE 1/2/3 -> RAW W [K][N], stored UNPERMUTED [k][n] (raw row kr at smem
//    row kr); fragments index k rows lq/lq+4/8+lq/12+lq directly (the permuted
//    A storage feeds hardware slot k exactly orig k, so raw B rows align).
//    Tile [16][136]: bank = (8*lq + n) mod 32 covers all banks, conflict-free.
// MODE 0: C = A@B (+R)
// MODE 1: MoE gate: gathered A rows -> gbuf (plain)
// MODE 2: MoE up:   gathered A; epi (two-pass): gb = silu(gb)*acc*score,
//                   tf32+permuted (gbuf becomes A of down GEMM)
// MODE 3: MoE down: A = gbuf slice; epi: atomicAdd into out
// MODE 4: fused QKV (concatenated wqkvT); C routed among q/k/v
#define TB 128
#define TSZ (128*16)
#define BRP 136
#define BRSZ (16*BRP)
#define STG 4
#define GEMM_SMEM_T ((STG*(TSZ+TSZ))*4 + TB*4)
#define GEMM_SMEM_R ((STG*(TSZ+BRSZ))*4 + TB*4)

template<int MODE>
__launch_bounds__(TB, 2)
__global__ void mma_gemm(const float* __restrict__ A, const float* __restrict__ BT,
                         const float* __restrict__ R, float* __restrict__ C,
                         int M, int N, int K,
                         const int* __restrict__ cnt, const int* __restrict__ elist,
                         const float* __restrict__ escore,
                         float* __restrict__ C2, float* __restrict__ C3) {
    constexpr bool RAWB = (MODE >= 1 && MODE <= 3);
    constexpr int BSZ = RAWB ? BRSZ : TSZ;
    extern __shared__ float sh[];
    float* As = sh;
    float* Bs = sh + STG * TSZ;
    int* rows = (int*)(sh + STG * (TSZ + BSZ));

    const int t = threadIdx.x;
    int e = 0, c = M;
    const int t0 = blockIdx.y * 128;
    const int by = t0;
    const int bx = blockIdx.x * 128;

    // output routing
    float* Cp = C; int cstr = N; int ccol = bx;
    if (MODE == 4) {
        if (bx < 1024)      { Cp = C;  cstr = 1024; ccol = bx; }
        else if (bx < 1280) { Cp = C2; cstr = 256;  ccol = bx - 1024; }
        else                { Cp = C3; cstr = 256;  ccol = bx - 1280; }
    }
    const float* Bp = BT;
    if (RAWB) {
        e = blockIdx.z;
        c = cnt[e];
        if (t0 >= c) return;
        Bp = BT + (size_t)e * K * N;
        if (MODE <= 2) {
            if (t < 128) {
                int tr = t0 + t;
                rows[t] = elist[e * NTOK + (tr < c ? tr : c - 1)];
            }
            __syncthreads();
        } else {
            A += (size_t)e * NTOK * K;
        }
    }

    const int lane = t & 31, warp = t >> 5;
    const int lr = lane >> 2, lq = lane & 3;
    const int m0w = (warp & 1) * 64, n0w = (warp >> 1) * 64;

    const uint32_t sAu = (uint32_t)__cvta_generic_to_shared(As);
    const uint32_t sBu = (uint32_t)__cvta_generic_to_shared(Bs);

    float acc[4][8][4] = {};
    const int KT = K / 16;

    auto issue = [&](int buf, int k0) {
        uint32_t dA = sAu + buf * TSZ * 4;
        uint32_t dB = sBu + buf * BSZ * 4;
        #pragma unroll
        for (int i = 0; i < 4; i++) {
            int f = i * TB + t;
            int r = f >> 2, seg = f & 3;
            int gr;
            if (MODE == 0 || MODE == 4) gr = by + r;
            else if (MODE == 3) gr = t0 + r;
            else gr = rows[r];
            cp16(dA + (r * 16 + seg * 4) * 4, A + (size_t)gr * K + k0 + seg * 4, 16);
            if (RAWB) {
                int kr = f >> 5, sg = f & 31;   // 16 raw k-rows x 32 16B-col-segments
                const float* srcB = Bp + (size_t)(k0 + kr) * N + bx + sg * 4;
                cp16(dB + (kr * BRP + sg * 4) * 4, srcB, 16);
            } else {
                int n = bx + r;
                const float* srcB = Bp + (size_t)(n < N ? n : 0) * K + k0 + seg * 4;
                cp16(dB + (r * 16 + seg * 4) * 4, srcB, n < N ? 16 : 0);
            }
        }
    };

    #pragma unroll
    for (int s = 0; s < STG - 1; s++) {
        issue(s, s * 16);
        asm volatile("cp.async.commit_group;");
    }
    for (int it = 0; it < KT; it++) {
        if (it + STG - 1 < KT) issue((it + STG - 1) % STG, (it + STG - 1) * 16);
        asm volatile("cp.async.commit_group;");
        asm volatile("cp.async.wait_group %0;" :: "n"(STG - 1));
        __syncthreads();
        const float* Ab = As + (it % STG) * TSZ;
        const float* Bb = Bs + (it % STG) * BSZ;

        uint32_t a0[4][4], a1[4][4];
        #pragma unroll
        for (int mt = 0; mt < 4; mt++) {
            int m = m0w + mt * 16 + lr;
            float4 va = *(const float4*)&Ab[m * 16 + 4 * lq];
            float4 vb = *(const float4*)&Ab[(m + 8) * 16 + 4 * lq];
            a0[mt][0] = __float_as_uint(va.x); a0[mt][1] = __float_as_uint(vb.x);
            a0[mt][2] = __float_as_uint(va.y); a0[mt][3] = __float_as_uint(vb.y);
            a1[mt][0] = __float_as_uint(va.z); a1[mt][1] = __float_as_uint(vb.z);
            a1[mt][2] = __float_as_uint(va.w); a1[mt][3] = __float_as_uint(vb.w);
        }
        uint32_t b0[8][2], b1[8][2];
        #pragma unroll
        for (int nt = 0; nt < 8; nt++) {
            int n = n0w + nt * 8 + lr;
            if (RAWB) {
                b0[nt][0] = ldcvt(&Bb[lq * BRP + n]);
                b0[nt][1] = ldcvt(&Bb[(lq + 4) * BRP + n]);
                b1[nt][0] = ldcvt(&Bb[(8 + lq) * BRP + n]);
                b1[nt][1] = ldcvt(&Bb[(12 + lq) * BRP + n]);
            } else {
                float4 vB = *(const float4*)&Bb[n * 16 + 4 * lq];
                b0[nt][0] = __float_as_uint(vB.x); b0[nt][1] = __float_as_uint(vB.y);
                b1[nt][0] = __float_as_uint(vB.z); b1[nt][1] = __float_as_uint(vB.w);
            }
        }
        #pragma unroll
        for (int mt = 0; mt < 4; mt++)
            #pragma unroll
            for (int nt = 0; nt < 8; nt++) {
                mma8(acc[mt][nt], a0[mt], b0[nt]);
                mma8(acc[mt][nt], a1[mt], b1[nt]);
            }
        __syncthreads();
    }

    // ---------------- epilogue ----------------
    if (MODE == 2) {
        // pass 1: read gate (plain layout), combine into acc. No writes yet —
        // the permuted store moves data across columns other threads still read.
        #pragma unroll
        for (int mt = 0; mt < 4; mt++)
            #pragma unroll
            for (int i = 0; i < 2; i++) {
                int r = m0w + mt * 16 + lr + i * 8;
                int tr = t0 + r;
                if (tr >= c) continue;
                float sc = escore[e * NTOK + tr];
                #pragma unroll
                for (int nt = 0; nt < 8; nt++) {
                    int col = bx + n0w + nt * 8 + lq * 2;
                    size_t o = ((size_t)e * NTOK + tr) * N + col;
                    float g0 = C[o], g1 = C[o + 1];
                    acc[mt][nt][i * 2]     = tf32r(g0 / (1.f + expf(-g0)) * acc[mt][nt][i * 2]     * sc);
                    acc[mt][nt][i * 2 + 1] = tf32r(g1 / (1.f + expf(-g1)) * acc[mt][nt][i * 2 + 1] * sc);
                }
            }
        __syncthreads();   // all reads complete before any permuted write
        // pass 2: write permuted (gbuf becomes A of down GEMM)
        #pragma unroll
        for (int mt = 0; mt < 4; mt++)
            #pragma unroll
            for (int i = 0; i < 2; i++) {
                int r = m0w + mt * 16 + lr + i * 8;
                int tr = t0 + r;
                if (tr >= c) continue;
                #pragma unroll
                for (int nt = 0; nt < 8; nt++) {
                    int col = bx + n0w + nt * 8 + lq * 2;
                    size_t ob = ((size_t)e * NTOK + tr) * N;
                    int pc = permc(col);
                    C[ob + pc]     = acc[mt][nt][i * 2];
                    C[ob + pc + 4] = acc[mt][nt][i * 2 + 1];  // permc(col+1)=permc(col)+4 for even col
                }
            }
        return;
    }
    #pragma unroll
    for (int mt = 0; mt < 4; mt++)
        #pragma unroll
        for (int i = 0; i < 2; i++) {
            int r = m0w + mt * 16 + lr + i * 8;
            #pragma unroll
            for (int nt = 0; nt < 8; nt++) {
                int col = ccol + n0w + nt * 8 + lq * 2;
                float v0 = acc[mt][nt][i * 2 + 0];
                float v1 = acc[mt][nt][i * 2 + 1];
                if (MODE == 0 || MODE == 4) {
                    if (col < cstr && (MODE == 4 || col < N)) {
                        int gr = by + r;
                        size_t o = (size_t)gr * cstr + col;
                        if (MODE == 0 && R) { v0 += R[o]; v1 += R[o + 1]; }
                        Cp[o] = v0; Cp[o + 1] = v1;
                    }
                } else {
                    int tr = t0 + r;
                    if (tr < c) {
                        int cc = bx + n0w + nt * 8 + lq * 2;
                        if (MODE == 1) {
                            size_t o = ((size_t)e * NTOK + tr) * N + cc;
                            C[o] = v0; C[o + 1] = v1;
                        } else {  // MODE 3
                            int n = elist[e * NTOK + tr];
                            atomicAdd(&C[(size_t)n * N + cc], v0);
                            atomicAdd(&C[(size_t)n * N + cc + 1], v1);
                        }
                    }
                }
            }
        }
}

// ---------------- RoPE (in place) -------------------------------------------
__global__ void rope_kernel(float* __restrict__ q, const float* __restrict__ cs,
                            const float* __restrict__ sn, int nheads) {
    int idx = blockIdx.x * blockDim.x + threadIdx.x;
    int total = NTOK * nheads * 32;
    if (idx >= total) return;
    int d  = idx & 31;
    int hh = (idx >> 5) % nheads;
    int n  = idx / (32 * nheads);
    int tp = n % TSEQ;
    float c0 = cs[tp * HEADD + d],      s0 = sn[tp * HEADD + d];
    float c1 = cs[tp * HEADD + d + 32], s1 = sn[tp * HEADD + d + 32];
    float* base = q + ((size_t)n * nheads + hh) * HEADD;
    float v0 = base[d], v1 = base[d + 32];
    base[d]      = v0 * c0 - v1 * s0;
    base[d + 32] = v1 * c1 + v0 * s1;
}

// ---------------- tiled causal flash attention ------------------------------
// Output written tf32-rounded + k-permuted (feeds Wo GEMM as A).
__global__ void attn_kernel(const float* __restrict__ Q, const float* __restrict__ Kg,
                            const float* __restrict__ Vg, float* __restrict__ O) {
    extern __shared__ float sm[];
    float* Qs = sm;                       // [64][65]
    float* Ks = sm + 64 * 65;             // [64][65]
    float* Vs = sm + 2 * 64 * 65;         // [64][68]
    float* Ss = sm + 2 * 64 * 65 + 64 * 68; // [64][65]
    __shared__ float m_s[64], l_s[64], corr_s[64];

    int qt = (int)gridDim.x - 1 - (int)blockIdx.x;
    int h = blockIdx.y, b = blockIdx.z;
    int kvh = h >> 2;
    int t = threadIdx.x, ty = t >> 4, tx = t & 15;
    int q0 = ty * 4, d0c = tx * 4;

    {
        int r = t >> 2, d0 = (t & 3) * 16;
        int n = b * TSEQ + qt * 64 + r;
        const float* src = Q + ((size_t)n * NHEAD + h) * 64 + d0;
        #pragma unroll
        for (int j = 0; j < 16; j += 4) {
            float4 v = *(const float4*)(src + j);
            Qs[r * 65 + d0 + j]     = v.x;
            Qs[r * 65 + d0 + j + 1] = v.y;
            Qs[r * 65 + d0 + j + 2] = v.z;
            Qs[r * 65 + d0 + j + 3] = v.w;
        }
    }
    if (t < 64) { m_s[t] = -1e30f; l_s[t] = 0.f; }

    float o[4][4];
    #pragma unroll
    for (int i = 0; i < 4; i++)
        #pragma unroll
        for (int j = 0; j < 4; j++) o[i][j] = 0.f;

    for (int kt = 0; kt <= qt; kt++) {
        __syncthreads();
        {
            int r = t >> 2, dd0 = (t & 3) * 16;
            int kn = b * TSEQ + kt * 64 + r;
            const float* ks = Kg + ((size_t)kn * NKVH + kvh) * 64 + dd0;
            const float* vs = Vg + ((size_t)kn * NKVH + kvh) * 64 + dd0;
            #pragma unroll
            for (int j = 0; j < 16; j += 4) {
                float4 kv = *(const float4*)(ks + j);
                Ks[r * 65 + dd0 + j]     = kv.x;
                Ks[r * 65 + dd0 + j + 1] = kv.y;
                Ks[r * 65 + dd0 + j + 2] = kv.z;
                Ks[r * 65 + dd0 + j + 3] = kv.w;
                float4 vv = *(const float4*)(vs + j);
                *(float4*)&Vs[r * 68 + dd0 + j] = vv;
            }
        }
        __syncthreads();
        float s4[4][4];
        #pragma unroll
        for (int i = 0; i < 4; i++)
            #pragma unroll
            for (int j = 0; j < 4; j++) s4[i][j] = 0.f;
        for (int d = 0; d < 64; d++) {
            float a[4], bb[4];
            #pragma unroll
            for (int i = 0; i < 4; i++) a[i] = Qs[(q0 + i) * 65 + d];
            #pragma unroll
            for (int j = 0; j < 4; j++) bb[j] = Ks[(d0c + j) * 65 + d];
            #pragma unroll
            for (int i = 0; i < 4; i++)
                #pragma unroll
                for (int j = 0; j < 4; j++) s4[i][j] += a[i] * bb[j];
        }
        #pragma unroll
        for (int i = 0; i < 4; i++)
            #pragma unroll
            for (int j = 0; j < 4; j++) {
                int kglob = kt * 64 + d0c + j, qglob = qt * 64 + q0 + i;
                Ss[(q0 + i) * 65 + d0c + j] =
                    (kglob <= qglob) ? s4[i][j] * 0.125f : -1e30f;
            }
        __syncthreads();
        if (t < 64) {
            float mx = -1e30f;
            for (int k = 0; k < 64; k++) mx = fmaxf(mx, Ss[t * 65 + k]);
            float newm = fmaxf(m_s[t], mx);
            float corr = expf(m_s[t] - newm);
            float sum = 0.f;
            for (int k = 0; k < 64; k++) sum += expf(Ss[t * 65 + k] - newm);
            l_s[t] = l_s[t] * corr + sum;
            m_s[t] = newm;
            corr_s[t] = corr;
        }
        __syncthreads();
        #pragma unroll
        for (int i = 0; i < 4; i++) {
            float nm = m_s[q0 + i];
            float cr = corr_s[q0 + i];
            #pragma unroll
            for (int j = 0; j < 4; j++) {
                float p = expf(Ss[(q0 + i) * 65 + d0c + j] - nm);
                Ss[(q0 + i) * 65 + d0c + j] = p;
                o[i][j] *= cr;
            }
        }
        __syncthreads();
        for (int k = 0; k < 64; k++) {
            float a[4];
            #pragma unroll
            for (int i = 0; i < 4; i++) a[i] = Ss[(q0 + i) * 65 + k];
            float4 bv = *(const float4*)&Vs[k * 68 + d0c];
            #pragma unroll
            for (int i = 0; i < 4; i++) {
                o[i][0] += a[i] * bv.x;
                o[i][1] += a[i] * bv.y;
                o[i][2] += a[i] * bv.z;
                o[i][3] += a[i] * bv.w;
            }
        }
    }
    #pragma unroll
    for (int i = 0; i < 4; i++) {
        float inv = 1.f / l_s[q0 + i];
        int n = b * TSEQ + qt * 64 + q0 + i;
        #pragma unroll
        for (int j = 0; j < 4; j++)
            O[(size_t)n * HDIM + permc(h * 64 + d0c + j)] = tf32r(o[i][j] * inv);
    }
}

// ---------------- router ----------------------------------------------------
__global__ void zero_cnt_kernel(int* __restrict__ cnt) {
    if (threadIdx.x < NEXP) cnt[threadIdx.x] = 0;
}

__global__ void router_topk_kernel(const float* __restrict__ logits,
                                   int* __restrict__ cnt, int* __restrict__ elist,
                                   float* __restrict__ escore) {
    int n = blockIdx.x * blockDim.x + threadIdx.x;
    if (n >= NTOK) return;
    float lg[NEXP];
    for (int e = 0; e < NEXP; e++) lg[e] = logits[(size_t)n * NEXP + e];
    int sel[TOPK]; float sv[TOPK];
    for (int k = 0; k < TOPK; k++) {
        float best = -1e30f; int bi = 0;
        for (int e = 0; e < NEXP; e++)
            if (lg[e] > best) { best = lg[e]; bi = e; }
        sel[k] = bi; sv[k] = best; lg[bi] = -1e30f;
    }
    float mx = sv[0];
    float ssum = 0.f;
    for (int k = 0; k < TOPK; k++) { sv[k] = expf(sv[k] - mx); ssum += sv[k]; }
    for (int k = 0; k < TOPK; k++) {
        int e = sel[k];
        int pos = atomicAdd(&cnt[e], 1);
        elist[e * NTOK + pos]  = n;
        escore[e * NTOK + pos] = sv[k] / ssum;
    }
}

// ---------------- launch ----------------------------------------------------
extern "C" void kernel_launch(void* const* d_in, const int* in_sizes, int n_in,
                              void* d_out, int out_size) {
    const float* x    = (const float*)d_in[0];
    const float* cosb = (const float*)d_in[1];
    const float* sinb = (const float*)d_in[2];
    const float* ln1  = (const float*)d_in[3];
    const float* ln2  = (const float*)d_in[4];
    const float* Wq   = (const float*)d_in[5];
    const float* Wk   = (const float*)d_in[6];
    const float* Wv   = (const float*)d_in[7];
    const float* Wo   = (const float*)d_in[8];
    const float* Wr   = (const float*)d_in[9];
    const float* Wg   = (const float*)d_in[10];
    const float* Wu   = (const float*)d_in[11];
    const float* Wd   = (const float*)d_in[12];
    float* out = (float*)d_out;
    float* rl  = out + (size_t)NTOK * HDIM;

    float *h, *q, *k, *v, *ao, *f, *gb, *es;
    float *wqkvT, *woT, *wrT;
    int *cnt, *el;
    cudaGetSymbolAddress((void**)&h,   g_h);
    cudaGetSymbolAddress((void**)&q,   g_q);
    cudaGetSymbolAddress((void**)&k,   g_k);
    cudaGetSymbolAddress((void**)&v,   g_v);
    cudaGetSymbolAddress((void**)&ao,  g_ao);
    cudaGetSymbolAddress((void**)&f,   g_f);
    cudaGetSymbolAddress((void**)&gb,  g_gbuf);
    cudaGetSymbolAddress((void**)&es,  g_escore);
    cudaGetSymbolAddress((void**)&cnt, g_cnt);
    cudaGetSymbolAddress((void**)&el,  g_elist);
    cudaGetSymbolAddress((void**)&wqkvT, g_wqkvT);
    cudaGetSymbolAddress((void**)&woT, g_woT);
    cudaGetSymbolAddress((void**)&wrT, g_wrT);

    const int ATTN_SMEM = (2 * 64 * 65 + 64 * 68 + 64 * 65) * 4;
    cudaFuncSetAttribute(attn_kernel, cudaFuncAttributeMaxDynamicSharedMemorySize,
                         ATTN_SMEM);
    cudaFuncSetAttribute(mma_gemm<0>, cudaFuncAttributeMaxDynamicSharedMemorySize, GEMM_SMEM_T);
    cudaFuncSetAttribute(mma_gemm<1>, cudaFuncAttributeMaxDynamicSharedMemorySize, GEMM_SMEM_R);
    cudaFuncSetAttribute(mma_gemm<2>, cudaFuncAttributeMaxDynamicSharedMemorySize, GEMM_SMEM_R);
    cudaFuncSetAttribute(mma_gemm<3>, cudaFuncAttributeMaxDynamicSharedMemorySize, GEMM_SMEM_R);
    cudaFuncSetAttribute(mma_gemm<4>, cudaFuncAttributeMaxDynamicSharedMemorySize, GEMM_SMEM_T);

    // 0. weight conversion — small dense weights ONLY (10MB; MoE stays raw)
    wconv_kernel<<<dim3(32, 32), 256>>>(Wq, wqkvT,               1024, 1024);
    wconv_kernel<<<dim3(8,  32), 256>>>(Wk, wqkvT + 1024 * 1024, 1024, 256);
    wconv_kernel<<<dim3(8,  32), 256>>>(Wv, wqkvT + 1280 * 1024, 1024, 256);
    wconv_kernel<<<dim3(32, 32), 256>>>(Wo, woT,                 1024, 1024);
    wconv_kernel<<<dim3(2,  32), 256>>>(Wr, wrT,                 1024, 64);

    // 1. h = rmsnorm(x, ln1_w)  [tf32 + permuted]
    rmsnorm_kernel<<<NTOK, 256>>>(x, ln1, h);
    // 2. fused QKV projection
    mma_gemm<4><<<dim3(12, 16), TB, GEMM_SMEM_T>>>(h, wqkvT, nullptr, q, NTOK, 1536, 1024,
                                                   nullptr, nullptr, nullptr, k, v);
    // 3. RoPE
    rope_kernel<<<(NTOK * NHEAD * 32 + 255) / 256, 256>>>(q, cosb, sinb, NHEAD);
    rope_kernel<<<(NTOK * NKVH  * 32 + 255) / 256, 256>>>(k, cosb, sinb, NKVH);
    // 4. attention (output tf32 + permuted)
    attn_kernel<<<dim3(TSEQ / 64, NHEAD, BATCH), 256, ATTN_SMEM>>>(q, k, v, ao);
    // 5. x1 = x + ao@Wo
    mma_gemm<0><<<dim3(8, 16), TB, GEMM_SMEM_T>>>(ao, woT, x, out, NTOK, 1024, 1024,
                                                  nullptr, nullptr, nullptr, nullptr, nullptr);
    // 6. f = rmsnorm(x1, ln2_w)  [tf32 + permuted]
    rmsnorm_kernel<<<NTOK, 256>>>(out, ln2, f);
    // 7. router logits
    mma_gemm<0><<<dim3(1, 16), TB, GEMM_SMEM_T>>>(f, wrT, nullptr, rl, NTOK, NEXP, 1024,
                                                  nullptr, nullptr, nullptr, nullptr, nullptr);
    // 8-9. top-k + expert lists
    zero_cnt_kernel<<<1, 64>>>(cnt);
    router_topk_kernel<<<NTOK / 256, 256>>>(rl, cnt, el, es);
    // 10a. gate GEMM (raw Wg) -> gbuf (plain)
    mma_gemm<1><<<dim3(IDIM / 128, NTOK / 128, NEXP), TB, GEMM_SMEM_R>>>(f, Wg, nullptr, gb, NTOK, IDIM, 1024,
                                                  cnt, el, es, nullptr, nullptr);
    // 10b. up GEMM (raw Wu), fused silu(gate)*up*score -> gbuf (tf32 + permuted, two-pass)
    mma_gemm<2><<<dim3(IDIM / 128, NTOK / 128, NEXP), TB, GEMM_SMEM_R>>>(f, Wu, nullptr, gb, NTOK, IDIM, 1024,
                                                  cnt, el, es, nullptr, nullptr);
    // 11. down GEMM (raw Wd) + scatter-add onto residual in d_out
    mma_gemm<3><<<dim3(HDIM / 128, NTOK / 128, NEXP), TB, GEMM_SMEM_R>>>(gb, Wd, nullptr, out, NTOK, HDIM, IDIM,
                                                  cnt, el, es, nullptr, nullptr);
}